// round 3
// baseline (speedup 1.0000x reference)
#include <cuda_runtime.h>
#include <cuda_bf16.h>

#define NROWS  8192
#define DIM    1024
#define NPAIRS 1024
#define MARGIN_RANK 0.05f
#define FULL   0xFFFFFFFFu

// ---------------- device scratch (no allocations allowed) ----------------
__device__ float  g_sp[NROWS];      // dp * rsqrt(|row|^2)   (text norm NOT applied)
__device__ float  g_sn[NROWS];      // dn * rsqrt(|row|^2)
__device__ float4 g_sorted[NROWS];  // {sim_pos, sim_neg, lev_bits, 0} bucket-sorted
__device__ int    g_bcount[NPAIRS];
__device__ int    g_bstart[NPAIRS];
__device__ float  g_cons_sum, g_pos_sum, g_neg_sum;
__device__ int    g_cons_cnt, g_rank_cnt;
__device__ int    g_done;

// ---------------- kA: row-norm + 2x GEMV (pure HBM stream) ---------------
__global__ void __launch_bounds__(256) kA_gemv(
    const float4* __restrict__ x, const float4* __restrict__ tp4,
    const float4* __restrict__ tn4)
{
    __shared__ float4 stp[DIM / 4], stn[DIM / 4];
    int t = threadIdx.x;
    stp[t] = tp4[t];
    stn[t] = tn4[t];
    __syncthreads();

    int warp = (blockIdx.x * 256 + t) >> 5;   // row id
    int lane = t & 31;
    const float4* row = x + (size_t)warp * (DIM / 4);

    float4 v[8];
    #pragma unroll
    for (int k = 0; k < 8; k++) v[k] = row[k * 32 + lane];   // 8 outstanding loads

    float dp = 0.f, dn = 0.f, dx = 0.f;
    #pragma unroll
    for (int k = 0; k < 8; k++) {
        float4 p = stp[k * 32 + lane];
        float4 q = stn[k * 32 + lane];
        dp += v[k].x*p.x + v[k].y*p.y + v[k].z*p.z + v[k].w*p.w;
        dn += v[k].x*q.x + v[k].y*q.y + v[k].z*q.z + v[k].w*q.w;
        dx += v[k].x*v[k].x + v[k].y*v[k].y + v[k].z*v[k].z + v[k].w*v[k].w;
    }
    #pragma unroll
    for (int o = 16; o; o >>= 1) {
        dp += __shfl_xor_sync(FULL, dp, o);
        dn += __shfl_xor_sync(FULL, dn, o);
        dx += __shfl_xor_sync(FULL, dx, o);
    }
    if (lane == 0) {
        float inv = rsqrtf(dx);
        g_sp[warp] = dp * inv;
        g_sn[warp] = dn * inv;
    }
}

// ---------------- kB: one block: norms + histogram + scan + SCATTER -------
__global__ void kB_prep(const float* __restrict__ tp, const float* __restrict__ tn,
                        const int* __restrict__ pair, const int* __restrict__ lev)
{
    __shared__ int   scnt[NPAIRS];   // histogram counts
    __shared__ int   sstart[NPAIRS]; // exclusive starts
    __shared__ int   wexcl[32];      // per-warp scan offsets
    __shared__ float sA[32], sB[32];
    __shared__ float s_invp, s_invn;

    int t = threadIdx.x;             // 1024 threads
    int lane = t & 31, w = t >> 5;
    scnt[t] = 0;
    if (t == 0) {
        g_cons_sum = 0.f; g_pos_sum = 0.f; g_neg_sum = 0.f;
        g_cons_cnt = 0;   g_rank_cnt = 0;  g_done = 0;
    }

    // text-vector inverse norms (t spans DIM exactly)
    float a = tp[t], b = tn[t];
    float pa = a * a, pb = b * b;
    #pragma unroll
    for (int o = 16; o; o >>= 1) {
        pa += __shfl_xor_sync(FULL, pa, o);
        pb += __shfl_xor_sync(FULL, pb, o);
    }
    if (lane == 0) { sA[w] = pa; sB[w] = pb; }
    __syncthreads();
    if (w == 0) {
        pa = sA[lane]; pb = sB[lane];
        #pragma unroll
        for (int o = 16; o; o >>= 1) {
            pa += __shfl_xor_sync(FULL, pa, o);
            pb += __shfl_xor_sync(FULL, pb, o);
        }
        if (lane == 0) { s_invp = rsqrtf(pa); s_invn = rsqrtf(pb); }
    }

    // histogram with rank capture (shared atomics, ~8-way contention)
    int myp[8], myr[8], myl[8];
    #pragma unroll
    for (int k = 0; k < 8; k++) {
        int i = t + k * NPAIRS;
        int p = pair[i];
        myp[k] = p;
        myl[k] = lev[i];
        myr[k] = atomicAdd(&scnt[p], 1);
    }
    __syncthreads();

    // hierarchical exclusive scan over 1024 counts
    int c = scnt[t];
    int v = c;
    #pragma unroll
    for (int o = 1; o < 32; o <<= 1) {
        int n = __shfl_up_sync(FULL, v, o);
        if (lane >= o) v += n;                 // inclusive within warp
    }
    if (lane == 31) wexcl[w] = v;              // warp totals
    __syncthreads();
    if (w == 0) {
        int orig = wexcl[lane];
        int x = orig;
        #pragma unroll
        for (int o = 1; o < 32; o <<= 1) {
            int n = __shfl_up_sync(FULL, x, o);
            if (lane >= o) x += n;
        }
        wexcl[lane] = x - orig;                // exclusive warp offset
    }
    __syncthreads();
    int start = wexcl[w] + v - c;              // exclusive global start
    sstart[t]   = start;
    g_bstart[t] = start;
    g_bcount[t] = c;
    __syncthreads();

    // fused scatter: coalesced reads of g_sp/g_sn, scattered float4 store
    float invp = s_invp, invn = s_invn;
    #pragma unroll
    for (int k = 0; k < 8; k++) {
        int i = t + k * NPAIRS;
        float4 o4;
        o4.x = g_sp[i] * invp;
        o4.y = g_sn[i] * invn;
        o4.z = __int_as_float(myl[k]);
        o4.w = 0.f;
        g_sorted[sstart[myp[k]] + myr[k]] = o4;
    }
}

// ---------------- kD: shuffle all-pairs per bucket + fused finalize -------
__global__ void __launch_bounds__(256) kD_pairs(float* __restrict__ out) {
    int wg   = (blockIdx.x * 256 + threadIdx.x) >> 5;  // bucket id
    int lane = threadIdx.x & 31;
    int start = g_bstart[wg];
    int c     = g_bcount[wg];

    float cs = 0.f, ps = 0.f, ns = 0.f;
    int cc = 0, rc = 0;

    if (c <= 32) {
        // one element per lane; all-pairs via shuffle broadcast (no memory in loop)
        float sp = 0.f, sn = 0.f; int lv = 0;
        if (lane < c) {
            float4 va = g_sorted[start + lane];
            sp = va.x; sn = va.y; lv = __float_as_int(va.z);
        }
        bool act = lane < c;
        for (int b = 0; b < c; b++) {
            float spb = __shfl_sync(FULL, sp, b);
            float snb = __shfl_sync(FULL, sn, b);
            int   lb  = __shfl_sync(FULL, lv, b);
            if (act && lv == lb && lane < b) {
                cs += fabsf(sp - spb) + fabsf(sn - snb);
                cc++;
            }
            if (act && lv < lb) {
                ps += fmaxf(MARGIN_RANK - (sp - spb), 0.f);
                ns += fmaxf(MARGIN_RANK + (sn - snb), 0.f);
                rc++;
            }
        }
    } else {
        // fallback for improbable large buckets
        for (int a = lane; a < c; a += 32) {
            float4 va = g_sorted[start + a];
            int la = __float_as_int(va.z);
            for (int b = 0; b < c; b++) {
                float4 vb = g_sorted[start + b];
                int lb = __float_as_int(vb.z);
                if (la == lb && a < b) {
                    cs += fabsf(va.x - vb.x) + fabsf(va.y - vb.y);
                    cc++;
                }
                if (la < lb) {
                    ps += fmaxf(MARGIN_RANK - (va.x - vb.x), 0.f);
                    ns += fmaxf(MARGIN_RANK + (va.y - vb.y), 0.f);
                    rc++;
                }
            }
        }
    }

    #pragma unroll
    for (int o = 16; o; o >>= 1) {
        cs += __shfl_xor_sync(FULL, cs, o);
        ps += __shfl_xor_sync(FULL, ps, o);
        ns += __shfl_xor_sync(FULL, ns, o);
        cc += __shfl_xor_sync(FULL, cc, o);
        rc += __shfl_xor_sync(FULL, rc, o);
    }
    if (lane == 0 && (cc | rc)) {
        atomicAdd(&g_cons_sum, cs);
        atomicAdd(&g_pos_sum,  ps);
        atomicAdd(&g_neg_sum,  ns);
        atomicAdd(&g_cons_cnt, cc);
        atomicAdd(&g_rank_cnt, rc);
    }

    // fused finalize: last block writes the scalar
    __syncthreads();
    if (threadIdx.x == 0) {
        __threadfence();
        if (atomicAdd(&g_done, 1) == (int)gridDim.x - 1) {
            __threadfence();
            float lc = (g_cons_cnt > 0) ? g_cons_sum / (float)(2 * g_cons_cnt) : 0.f;
            float lp = (g_rank_cnt > 0) ? g_pos_sum  / (float)g_rank_cnt       : 0.f;
            float ln = (g_rank_cnt > 0) ? g_neg_sum  / (float)g_rank_cnt       : 0.f;
            out[0] = lc + lp + ln;
        }
    }
}

// ---------------- launch ---------------------------------------------------
extern "C" void kernel_launch(void* const* d_in, const int* in_sizes, int n_in,
                              void* d_out, int out_size) {
    const float* img  = (const float*)d_in[0];  // [8192, 1024]
    const float* tp   = (const float*)d_in[1];  // [1024]
    const float* tn   = (const float*)d_in[2];  // [1024]
    const int*   lev  = (const int*)  d_in[3];  // [8192]
    const int*   pair = (const int*)  d_in[4];  // [8192]
    float* out = (float*)d_out;

    kA_gemv<<<(NROWS * 32) / 256, 256>>>(
        (const float4*)img, (const float4*)tp, (const float4*)tn);
    kB_prep<<<1, NPAIRS>>>(tp, tn, pair, lev);
    kD_pairs<<<(NPAIRS * 32) / 256, 256>>>(out);
}

// round 4
// speedup vs baseline: 1.2122x; 1.2122x over previous
#include <cuda_runtime.h>
#include <cuda_bf16.h>

#define NROWS  8192
#define DIM    1024
#define NPAIRS 1024
#define MARGIN_RANK 0.05f
#define FULL   0xFFFFFFFFu

// ---------------- device scratch (no allocations allowed) ----------------
__device__ int    g_pos[NROWS];     // destination slot in bucket-sorted order
__device__ float4 g_sorted[NROWS];  // {sim_pos, sim_neg, lev_bits, 0} bucket-sorted
__device__ int    g_bcount[NPAIRS];
__device__ int    g_bstart[NPAIRS];
__device__ float  g_invp, g_invn;   // text-vector inverse norms
__device__ float  g_cons_sum, g_pos_sum, g_neg_sum;
__device__ int    g_cons_cnt, g_rank_cnt;
__device__ int    g_done;

// ---------------- kB: positions + text norms (independent of kA) ----------
// One 1024-thread block: zero accumulators, text inverse-norms, histogram of
// pair[] with rank capture via shared atomics, hierarchical scan, coalesced
// write of g_pos.  Touches only pair[] + tp + tn (~40 KB).
__global__ void kB_prep(const float* __restrict__ tp, const float* __restrict__ tn,
                        const int* __restrict__ pair)
{
    __shared__ int   scnt[NPAIRS];   // histogram counts
    __shared__ int   sstart[NPAIRS]; // exclusive starts
    __shared__ int   wexcl[32];      // per-warp scan offsets
    __shared__ float sA[32], sB[32];

    int t = threadIdx.x;             // 1024 threads
    int lane = t & 31, w = t >> 5;

    // issue all global loads up front (overlap DRAM latency with setup)
    int myp[8];
    #pragma unroll
    for (int k = 0; k < 8; k++) myp[k] = pair[t + k * NPAIRS];
    float a = tp[t], b = tn[t];

    scnt[t] = 0;
    if (t == 0) {
        g_cons_sum = 0.f; g_pos_sum = 0.f; g_neg_sum = 0.f;
        g_cons_cnt = 0;   g_rank_cnt = 0;  g_done = 0;
    }

    // text-vector inverse norms (t spans DIM exactly)
    float pa = a * a, pb = b * b;
    #pragma unroll
    for (int o = 16; o; o >>= 1) {
        pa += __shfl_xor_sync(FULL, pa, o);
        pb += __shfl_xor_sync(FULL, pb, o);
    }
    if (lane == 0) { sA[w] = pa; sB[w] = pb; }
    __syncthreads();
    if (w == 0) {
        pa = sA[lane]; pb = sB[lane];
        #pragma unroll
        for (int o = 16; o; o >>= 1) {
            pa += __shfl_xor_sync(FULL, pa, o);
            pb += __shfl_xor_sync(FULL, pb, o);
        }
        if (lane == 0) { g_invp = rsqrtf(pa); g_invn = rsqrtf(pb); }
    }

    // histogram with rank capture (shared atomics, low contention)
    int myr[8];
    #pragma unroll
    for (int k = 0; k < 8; k++)
        myr[k] = atomicAdd(&scnt[myp[k]], 1);
    __syncthreads();

    // hierarchical exclusive scan over 1024 counts
    int c = scnt[t];
    int v = c;
    #pragma unroll
    for (int o = 1; o < 32; o <<= 1) {
        int n = __shfl_up_sync(FULL, v, o);
        if (lane >= o) v += n;                 // inclusive within warp
    }
    if (lane == 31) wexcl[w] = v;              // warp totals
    __syncthreads();
    if (w == 0) {
        int orig = wexcl[lane];
        int x = orig;
        #pragma unroll
        for (int o = 1; o < 32; o <<= 1) {
            int n = __shfl_up_sync(FULL, x, o);
            if (lane >= o) x += n;
        }
        wexcl[lane] = x - orig;                // exclusive warp offset
    }
    __syncthreads();
    int start = wexcl[w] + v - c;              // exclusive global start
    sstart[t]   = start;
    g_bstart[t] = start;
    g_bcount[t] = c;
    __syncthreads();

    // coalesced positions
    #pragma unroll
    for (int k = 0; k < 8; k++)
        g_pos[t + k * NPAIRS] = sstart[myp[k]] + myr[k];
}

// ---------------- kA: row-norm + 2x GEMV + fused scatter ------------------
// One warp per row.  Row loads are issued BEFORE smem staging so the block
// barrier overlaps DRAM latency.  Lane 0 writes the bucket-sorted record
// directly (no g_sp/g_sn round-trip).
__global__ void __launch_bounds__(256) kA_gemv(
    const float4* __restrict__ x, const float4* __restrict__ tp4,
    const float4* __restrict__ tn4, const int* __restrict__ lev)
{
    __shared__ float4 stp[DIM / 4], stn[DIM / 4];
    int t = threadIdx.x;
    int warp = (blockIdx.x * 256 + t) >> 5;   // row id
    int lane = t & 31;
    const float4* row = x + (size_t)warp * (DIM / 4);

    // 8 independent row loads in flight first
    float4 v[8];
    #pragma unroll
    for (int k = 0; k < 8; k++) v[k] = row[k * 32 + lane];

    // stage text vectors while row loads are in flight
    stp[t] = tp4[t];
    stn[t] = tn4[t];
    __syncthreads();

    float dp = 0.f, dn = 0.f, dx = 0.f;
    #pragma unroll
    for (int k = 0; k < 8; k++) {
        float4 p = stp[k * 32 + lane];
        float4 q = stn[k * 32 + lane];
        dp += v[k].x*p.x + v[k].y*p.y + v[k].z*p.z + v[k].w*p.w;
        dn += v[k].x*q.x + v[k].y*q.y + v[k].z*q.z + v[k].w*q.w;
        dx += v[k].x*v[k].x + v[k].y*v[k].y + v[k].z*v[k].z + v[k].w*v[k].w;
    }
    #pragma unroll
    for (int o = 16; o; o >>= 1) {
        dp += __shfl_xor_sync(FULL, dp, o);
        dn += __shfl_xor_sync(FULL, dn, o);
        dx += __shfl_xor_sync(FULL, dx, o);
    }
    if (lane == 0) {
        float inv = rsqrtf(dx);
        float4 o4;
        o4.x = dp * inv * g_invp;
        o4.y = dn * inv * g_invn;
        o4.z = __int_as_float(lev[warp]);
        o4.w = 0.f;
        g_sorted[g_pos[warp]] = o4;
    }
}

// ---------------- kD: shuffle all-pairs per bucket + fused finalize -------
__global__ void __launch_bounds__(256) kD_pairs(float* __restrict__ out) {
    int wg   = (blockIdx.x * 256 + threadIdx.x) >> 5;  // bucket id
    int lane = threadIdx.x & 31;
    int start = g_bstart[wg];
    int c     = g_bcount[wg];

    float cs = 0.f, ps = 0.f, ns = 0.f;
    int cc = 0, rc = 0;

    if (c <= 32) {
        // one element per lane; all-pairs via shuffle broadcast (no memory in loop)
        float sp = 0.f, sn = 0.f; int lv = 0;
        if (lane < c) {
            float4 va = g_sorted[start + lane];
            sp = va.x; sn = va.y; lv = __float_as_int(va.z);
        }
        bool act = lane < c;
        for (int b = 0; b < c; b++) {
            float spb = __shfl_sync(FULL, sp, b);
            float snb = __shfl_sync(FULL, sn, b);
            int   lb  = __shfl_sync(FULL, lv, b);
            if (act && lv == lb && lane < b) {
                cs += fabsf(sp - spb) + fabsf(sn - snb);
                cc++;
            }
            if (act && lv < lb) {
                ps += fmaxf(MARGIN_RANK - (sp - spb), 0.f);
                ns += fmaxf(MARGIN_RANK + (sn - snb), 0.f);
                rc++;
            }
        }
    } else {
        // fallback for improbable large buckets
        for (int a = lane; a < c; a += 32) {
            float4 va = g_sorted[start + a];
            int la = __float_as_int(va.z);
            for (int b = 0; b < c; b++) {
                float4 vb = g_sorted[start + b];
                int lb = __float_as_int(vb.z);
                if (la == lb && a < b) {
                    cs += fabsf(va.x - vb.x) + fabsf(va.y - vb.y);
                    cc++;
                }
                if (la < lb) {
                    ps += fmaxf(MARGIN_RANK - (va.x - vb.x), 0.f);
                    ns += fmaxf(MARGIN_RANK + (va.y - vb.y), 0.f);
                    rc++;
                }
            }
        }
    }

    #pragma unroll
    for (int o = 16; o; o >>= 1) {
        cs += __shfl_xor_sync(FULL, cs, o);
        ps += __shfl_xor_sync(FULL, ps, o);
        ns += __shfl_xor_sync(FULL, ns, o);
        cc += __shfl_xor_sync(FULL, cc, o);
        rc += __shfl_xor_sync(FULL, rc, o);
    }
    if (lane == 0 && (cc | rc)) {
        atomicAdd(&g_cons_sum, cs);
        atomicAdd(&g_pos_sum,  ps);
        atomicAdd(&g_neg_sum,  ns);
        atomicAdd(&g_cons_cnt, cc);
        atomicAdd(&g_rank_cnt, rc);
    }

    // fused finalize: last block writes the scalar
    __syncthreads();
    if (threadIdx.x == 0) {
        __threadfence();
        if (atomicAdd(&g_done, 1) == (int)gridDim.x - 1) {
            __threadfence();
            float lc = (g_cons_cnt > 0) ? g_cons_sum / (float)(2 * g_cons_cnt) : 0.f;
            float lp = (g_rank_cnt > 0) ? g_pos_sum  / (float)g_rank_cnt       : 0.f;
            float ln = (g_rank_cnt > 0) ? g_neg_sum  / (float)g_rank_cnt       : 0.f;
            out[0] = lc + lp + ln;
        }
    }
}

// ---------------- launch ---------------------------------------------------
extern "C" void kernel_launch(void* const* d_in, const int* in_sizes, int n_in,
                              void* d_out, int out_size) {
    const float* img  = (const float*)d_in[0];  // [8192, 1024]
    const float* tp   = (const float*)d_in[1];  // [1024]
    const float* tn   = (const float*)d_in[2];  // [1024]
    const int*   lev  = (const int*)  d_in[3];  // [8192]
    const int*   pair = (const int*)  d_in[4];  // [8192]
    float* out = (float*)d_out;

    kB_prep<<<1, NPAIRS>>>(tp, tn, pair);
    kA_gemv<<<(NROWS * 32) / 256, 256>>>(
        (const float4*)img, (const float4*)tp, (const float4*)tn, lev);
    kD_pairs<<<(NPAIRS * 32) / 256, 256>>>(out);
}